// round 2
// baseline (speedup 1.0000x reference)
#include <cuda_runtime.h>

#define BB 64
#define VV 2000
#define FF 8
#define GG 80
#define NROT 5
#define DD (FF*GG)          // 640
#define NSLICE 4
#define TPB (GG*NSLICE)     // 320
#define JSPLIT 2
#define TPB2 (DD/JSPLIT)    // 320
#define TWO_PI_F 6.283185307179586f
#define EPSF 1e-5f

// scratch for per-rotation descriptors (no dynamic allocation allowed)
__device__ float g_desc[NROT][BB][DD];

// ---------------------------------------------------------------------------
// Kernel A: per (b, rotation k) compute normalized gaussian descriptor
//   desc[b,k,f*G+g] = (sum_v w[v,g]*feat[v,f]) / (sum_v w[v,g] + eps)
//   w = exp(-(rho-mu_r)^2/(sr^2+eps) - (th-mu_t)^2/(st^2+eps)) * mask
// One exp per (v,g); quadratic expanded so inner loop is 4 FMA + EX2 + 10 FMA.
// ---------------------------------------------------------------------------
__global__ void __launch_bounds__(TPB)
gauss_desc_kernel(const float* __restrict__ feat,
                  const float* __restrict__ rho,
                  const float* __restrict__ theta,
                  const float* __restrict__ mask,
                  const float* __restrict__ mu_rho,
                  const float* __restrict__ sigma_rho,
                  const float* __restrict__ mu_theta,
                  const float* __restrict__ sigma_theta)
{
    extern __shared__ float smem[];
    float* s_rho  = smem;            // [VV]
    float* s_rho2 = smem + VV;       // [VV]
    float* s_th   = smem + 2*VV;     // [VV]
    float* s_th2  = smem + 3*VV;     // [VV]
    float* s_mask = smem + 4*VV;     // [VV]
    float* s_feat = smem + 5*VV;     // [VV*FF], 16B aligned (5*VV*4 = 40000)

    const int bk  = blockIdx.x;
    const int b   = bk / NROT;
    const int k   = bk % NROT;
    const int tid = threadIdx.x;
    const float kdelta = (float)k * (TWO_PI_F / (float)NROT);

    // stage per-batch vertex data
    for (int v = tid; v < VV; v += TPB) {
        float r = rho[b*VV + v];
        s_rho[v]  = r;
        s_rho2[v] = r * r;
        float t = theta[b*VV + v] + kdelta;
        if (t >= TWO_PI_F) t -= TWO_PI_F;     // jnp.mod(theta + k*d, 2pi), theta in [0,2pi)
        s_th[v]  = t;
        s_th2[v] = t * t;
        s_mask[v] = mask[b*VV + v];
    }
    for (int i = tid; i < VV*FF; i += TPB)
        s_feat[i] = feat[b*VV*FF + i];
    __syncthreads();

    const int g = tid % GG;          // gaussian owned by this thread
    const int s = tid / GG;          // v-slice 0..3

    const float mur = mu_rho[g];
    const float mut = mu_theta[g];
    const float sr  = sigma_rho[g];
    const float st  = sigma_theta[g];
    const float isr = 1.0f / (sr*sr + EPSF);
    const float ist = 1.0f / (st*st + EPSF);
    // arg = -(rho-mur)^2*isr - (th-mut)^2*ist
    //     = c0 + c1*rho + c2*th - isr*rho^2 - ist*th^2
    const float c1 = 2.0f * mur * isr;
    const float c2 = 2.0f * mut * ist;
    const float c0 = -(mur*mur*isr + mut*mut*ist);

    float a0 = 0.0f;
    float af[FF];
    #pragma unroll
    for (int f = 0; f < FF; f++) af[f] = 0.0f;

    for (int v = s; v < VV; v += NSLICE) {
        float arg = fmaf(c1,  s_rho[v],  c0);
        arg       = fmaf(c2,  s_th[v],   arg);
        arg       = fmaf(-isr, s_rho2[v], arg);
        arg       = fmaf(-ist, s_th2[v],  arg);
        float w = __expf(arg) * s_mask[v];
        a0 += w;
        float4 f0 = *(const float4*)(s_feat + v*FF);
        float4 f1 = *(const float4*)(s_feat + v*FF + 4);
        af[0] = fmaf(w, f0.x, af[0]);
        af[1] = fmaf(w, f0.y, af[1]);
        af[2] = fmaf(w, f0.z, af[2]);
        af[3] = fmaf(w, f0.w, af[3]);
        af[4] = fmaf(w, f1.x, af[4]);
        af[5] = fmaf(w, f1.y, af[5]);
        af[6] = fmaf(w, f1.z, af[6]);
        af[7] = fmaf(w, f1.w, af[7]);
    }
    __syncthreads();          // vertex data no longer needed; reuse smem

    float* red = smem;        // [9][TPB] = 11.5 KB
    red[0*TPB + tid] = a0;
    #pragma unroll
    for (int f = 0; f < FF; f++) red[(1+f)*TPB + tid] = af[f];
    __syncthreads();

    if (tid < GG) {
        float S0 = 0.0f;
        #pragma unroll
        for (int ss = 0; ss < NSLICE; ss++) S0 += red[0*TPB + ss*GG + tid];
        float inv = 1.0f / (S0 + EPSF);
        #pragma unroll
        for (int f = 0; f < FF; f++) {
            float Sf = 0.0f;
            #pragma unroll
            for (int ss = 0; ss < NSLICE; ss++) Sf += red[(1+f)*TPB + ss*GG + tid];
            g_desc[k][b][f*GG + tid] = Sf * inv;   // reshape [B,F,G] -> f*G+g
        }
    }
}

// ---------------------------------------------------------------------------
// Kernel B: out[b,j] = relu(max_k (desc_k[b,:] @ W[:,j]) + bias[j])
// 5 rotation accumulators per thread so each W element is loaded once per block.
// ---------------------------------------------------------------------------
__global__ void __launch_bounds__(TPB2)
gemm_max_relu_kernel(const float* __restrict__ Wm,
                     const float* __restrict__ bias,
                     float* __restrict__ out)
{
    __shared__ float s_desc[NROT][DD];     // 12.8 KB
    const int b   = blockIdx.x;
    const int tid = threadIdx.x;

    for (int idx = tid; idx < NROT*DD; idx += TPB2) {
        int k = idx / DD, i = idx - k*DD;
        s_desc[k][i] = g_desc[k][b][i];
    }
    __syncthreads();

    const int j = blockIdx.y * TPB2 + tid;
    float acc0 = 0.f, acc1 = 0.f, acc2 = 0.f, acc3 = 0.f, acc4 = 0.f;
    const float bj = bias[j];

    const float4* sd0 = (const float4*)s_desc[0];
    const float4* sd1 = (const float4*)s_desc[1];
    const float4* sd2 = (const float4*)s_desc[2];
    const float4* sd3 = (const float4*)s_desc[3];
    const float4* sd4 = (const float4*)s_desc[4];

    #pragma unroll 4
    for (int i4 = 0; i4 < DD/4; i4++) {
        const int i = i4 * 4;
        float w0 = Wm[(i+0)*DD + j];
        float w1 = Wm[(i+1)*DD + j];
        float w2 = Wm[(i+2)*DD + j];
        float w3 = Wm[(i+3)*DD + j];
        float4 d;
        d = sd0[i4];
        acc0 = fmaf(d.x, w0, acc0); acc0 = fmaf(d.y, w1, acc0);
        acc0 = fmaf(d.z, w2, acc0); acc0 = fmaf(d.w, w3, acc0);
        d = sd1[i4];
        acc1 = fmaf(d.x, w0, acc1); acc1 = fmaf(d.y, w1, acc1);
        acc1 = fmaf(d.z, w2, acc1); acc1 = fmaf(d.w, w3, acc1);
        d = sd2[i4];
        acc2 = fmaf(d.x, w0, acc2); acc2 = fmaf(d.y, w1, acc2);
        acc2 = fmaf(d.z, w2, acc2); acc2 = fmaf(d.w, w3, acc2);
        d = sd3[i4];
        acc3 = fmaf(d.x, w0, acc3); acc3 = fmaf(d.y, w1, acc3);
        acc3 = fmaf(d.z, w2, acc3); acc3 = fmaf(d.w, w3, acc3);
        d = sd4[i4];
        acc4 = fmaf(d.x, w0, acc4); acc4 = fmaf(d.y, w1, acc4);
        acc4 = fmaf(d.z, w2, acc4); acc4 = fmaf(d.w, w3, acc4);
    }

    float m = fmaxf(fmaxf(fmaxf(acc0, acc1), fmaxf(acc2, acc3)), acc4);
    out[b*DD + j] = fmaxf(m + bj, 0.0f);
}

// ---------------------------------------------------------------------------

extern "C" void kernel_launch(void* const* d_in, const int* in_sizes, int n_in,
                              void* d_out, int out_size) {
    const float* feat        = (const float*)d_in[0];
    const float* rho         = (const float*)d_in[1];
    const float* theta       = (const float*)d_in[2];
    const float* mask        = (const float*)d_in[3];
    const float* mu_rho      = (const float*)d_in[4];
    const float* sigma_rho   = (const float*)d_in[5];
    const float* mu_theta    = (const float*)d_in[6];
    const float* sigma_theta = (const float*)d_in[7];
    const float* Wm          = (const float*)d_in[8];
    const float* bias        = (const float*)d_in[9];
    float* out = (float*)d_out;

    const size_t smemA = (size_t)(5*VV + VV*FF) * sizeof(float);  // 104000 B
    cudaFuncSetAttribute(gauss_desc_kernel,
                         cudaFuncAttributeMaxDynamicSharedMemorySize, (int)smemA);

    gauss_desc_kernel<<<BB*NROT, TPB, smemA>>>(
        feat, rho, theta, mask, mu_rho, sigma_rho, mu_theta, sigma_theta);

    gemm_max_relu_kernel<<<dim3(BB, JSPLIT), TPB2>>>(Wm, bias, out);
}

// round 3
// speedup vs baseline: 2.3512x; 2.3512x over previous
#include <cuda_runtime.h>

#define BB 64
#define VV 2000
#define FF 8
#define GG 80
#define NROT 5
#define DD (FF*GG)          // 640
#define VCH 4               // vertex chunks per (b,k)
#define VCS (VV/VCH)        // 500 vertices per chunk
#define NSLICE 4
#define TPB (GG*NSLICE)     // 320 threads kernel A
#define TPBB 128            // threads kernel B
#define JT 5                // j tiles of 128
#define BG 32               // b groups of 2
#define TWO_PI_F 6.283185307179586f
#define EPSF 1e-5f

// partial (unnormalized) sums: [bk][chunk][9][G]  (j=0: sum w; j=1..8: sum w*feat_f)
__device__ float g_part[BB*NROT][VCH][9][GG];

// ---------------------------------------------------------------------------
// packed f32x2 helpers (FFMA2 path, PTX-only)
// ---------------------------------------------------------------------------
__device__ __forceinline__ unsigned long long pack2(float lo, float hi) {
    unsigned long long r;
    asm("mov.b64 %0, {%1, %2};" : "=l"(r) : "f"(lo), "f"(hi));
    return r;
}
__device__ __forceinline__ void fma2(unsigned long long& d,
                                     unsigned long long a,
                                     unsigned long long b) {
    asm("fma.rn.f32x2 %0, %1, %2, %3;" : "=l"(d) : "l"(a), "l"(b), "l"(d));
}
__device__ __forceinline__ float2 unpack2(unsigned long long v) {
    float lo, hi;
    asm("mov.b64 {%0, %1}, %2;" : "=f"(lo), "=f"(hi) : "l"(v));
    return make_float2(lo, hi);
}

// ---------------------------------------------------------------------------
// Kernel A: per (b, rotation k, v-chunk) accumulate gaussian-weighted sums.
//   w = exp(c0 + c1*rho - isr*rho^2 + c2*th - ist*th^2) * mask
//   partial[0] += w ; partial[1+f] += w*feat_f   (packed f32x2 accumulate)
// ---------------------------------------------------------------------------
__global__ void __launch_bounds__(TPB)
gauss_desc_kernel(const float* __restrict__ feat,
                  const float* __restrict__ rho,
                  const float* __restrict__ theta,
                  const float* __restrict__ mask,
                  const float* __restrict__ mu_rho,
                  const float* __restrict__ sigma_rho,
                  const float* __restrict__ mu_theta,
                  const float* __restrict__ sigma_theta)
{
    __shared__ float4 s_pack[VCS];                    // {rho, rho^2, th, th^2}
    __shared__ float  s_mask[VCS];
    __shared__ __align__(16) float s_feat[VCS*FF];
    __shared__ float  red[9][TPB];

    const int bk  = blockIdx.x;
    const int b   = bk / NROT;
    const int k   = bk % NROT;
    const int cv0 = blockIdx.y * VCS;
    const int tid = threadIdx.x;
    const float kdelta = (float)k * (TWO_PI_F / (float)NROT);

    for (int v = tid; v < VCS; v += TPB) {
        float r = rho[b*VV + cv0 + v];
        float t = theta[b*VV + cv0 + v] + kdelta;
        if (t >= TWO_PI_F) t -= TWO_PI_F;             // theta in [0,2pi)
        s_pack[v] = make_float4(r, r*r, t, t*t);
        s_mask[v] = mask[b*VV + cv0 + v];
    }
    for (int i = tid; i < VCS*FF; i += TPB)
        s_feat[i] = feat[(b*VV + cv0)*FF + i];
    __syncthreads();

    const int g = tid % GG;
    const int s = tid / GG;

    const float mur = mu_rho[g];
    const float mut = mu_theta[g];
    const float sr  = sigma_rho[g];
    const float st  = sigma_theta[g];
    const float isr = 1.0f / (sr*sr + EPSF);
    const float ist = 1.0f / (st*st + EPSF);
    const float c1  = 2.0f * mur * isr;
    const float c2  = 2.0f * mut * ist;
    const float c0  = -(mur*mur*isr + mut*mut*ist);

    float a0 = 0.0f;
    unsigned long long acc[4] = {0ull, 0ull, 0ull, 0ull};  // 8 feature accs packed

    for (int v = s; v < VCS; v += NSLICE) {
        float4 p = s_pack[v];
        float arg = fmaf(c1,  p.x, c0);
        arg       = fmaf(-isr, p.y, arg);
        arg       = fmaf(c2,  p.z, arg);
        arg       = fmaf(-ist, p.w, arg);
        float w = __expf(arg) * s_mask[v];
        a0 += w;
        unsigned long long w2 = pack2(w, w);
        const ulonglong2* fp = (const ulonglong2*)(s_feat + v*FF);
        ulonglong2 q0 = fp[0];
        ulonglong2 q1 = fp[1];
        fma2(acc[0], w2, q0.x);
        fma2(acc[1], w2, q0.y);
        fma2(acc[2], w2, q1.x);
        fma2(acc[3], w2, q1.y);
    }

    red[0][tid] = a0;
    #pragma unroll
    for (int a = 0; a < 4; a++) {
        float2 u = unpack2(acc[a]);
        red[1 + 2*a][tid]     = u.x;
        red[2 + 2*a][tid]     = u.y;
    }
    __syncthreads();

    for (int e = tid; e < 9*GG; e += TPB) {
        int j  = e / GG;
        int gg = e % GG;
        float Sv = red[j][gg] + red[j][GG + gg] + red[j][2*GG + gg] + red[j][3*GG + gg];
        g_part[bk][blockIdx.y][j][gg] = Sv;
    }
}

// ---------------------------------------------------------------------------
// Kernel B: normalize descriptors, then out[b,j] = relu(max_k desc_k@W[:,j] + b[j])
// Block = (j-tile of 128) x (pair of b). 10 packed accumulators per thread so
// each W element is read once per block; accs pack over i-pairs.
// ---------------------------------------------------------------------------
__global__ void __launch_bounds__(TPBB)
gemm_max_relu_kernel(const float* __restrict__ Wm,
                     const float* __restrict__ bias,
                     float* __restrict__ out)
{
    __shared__ __align__(16) float s_desc[2][NROT][DD];   // 25.6 KB
    const int tid = threadIdx.x;
    const int b0  = blockIdx.y * 2;

    // load + chunk-sum + normalize descriptors for 2 b's x 5 rotations
    for (int e = tid; e < 2*NROT*GG; e += TPBB) {
        int bb = e / (NROT*GG);
        int r  = e - bb*(NROT*GG);
        int k  = r / GG;
        int g  = r - k*GG;
        int bk = (b0 + bb)*NROT + k;
        float S[9];
        #pragma unroll
        for (int j = 0; j < 9; j++) S[j] = 0.0f;
        #pragma unroll
        for (int c = 0; c < VCH; c++) {
            #pragma unroll
            for (int j = 0; j < 9; j++) S[j] += g_part[bk][c][j][g];
        }
        float inv = 1.0f / (S[0] + EPSF);
        #pragma unroll
        for (int f = 0; f < FF; f++)
            s_desc[bb][k][f*GG + g] = S[1 + f] * inv;
    }
    __syncthreads();

    const int j = blockIdx.x * TPBB + tid;
    const float bj = bias[j];

    unsigned long long acc[10];
    #pragma unroll
    for (int a = 0; a < 10; a++) acc[a] = 0ull;

    #pragma unroll 2
    for (int i = 0; i < DD; i += 4) {
        float w0 = Wm[(i+0)*DD + j];
        float w1 = Wm[(i+1)*DD + j];
        float w2 = Wm[(i+2)*DD + j];
        float w3 = Wm[(i+3)*DD + j];
        unsigned long long wp0 = pack2(w0, w1);
        unsigned long long wp1 = pack2(w2, w3);
        #pragma unroll
        for (int bb = 0; bb < 2; bb++) {
            #pragma unroll
            for (int k = 0; k < NROT; k++) {
                ulonglong2 d = *(const ulonglong2*)&s_desc[bb][k][i];
                fma2(acc[bb*NROT + k], d.x, wp0);
                fma2(acc[bb*NROT + k], d.y, wp1);
            }
        }
    }

    #pragma unroll
    for (int bb = 0; bb < 2; bb++) {
        float m = -3.4e38f;
        #pragma unroll
        for (int k = 0; k < NROT; k++) {
            float2 u = unpack2(acc[bb*NROT + k]);
            m = fmaxf(m, u.x + u.y);
        }
        out[(b0 + bb)*DD + j] = fmaxf(m + bj, 0.0f);
    }
}

// ---------------------------------------------------------------------------

extern "C" void kernel_launch(void* const* d_in, const int* in_sizes, int n_in,
                              void* d_out, int out_size) {
    const float* feat        = (const float*)d_in[0];
    const float* rho         = (const float*)d_in[1];
    const float* theta       = (const float*)d_in[2];
    const float* mask        = (const float*)d_in[3];
    const float* mu_rho      = (const float*)d_in[4];
    const float* sigma_rho   = (const float*)d_in[5];
    const float* mu_theta    = (const float*)d_in[6];
    const float* sigma_theta = (const float*)d_in[7];
    const float* Wm          = (const float*)d_in[8];
    const float* bias        = (const float*)d_in[9];
    float* out = (float*)d_out;

    gauss_desc_kernel<<<dim3(BB*NROT, VCH), TPB>>>(
        feat, rho, theta, mask, mu_rho, sigma_rho, mu_theta, sigma_theta);

    gemm_max_relu_kernel<<<dim3(JT, BG), TPBB>>>(Wm, bias, out);
}